// round 3
// baseline (speedup 1.0000x reference)
#include <cuda_runtime.h>

// Problem shape (fixed)
#define B_   32
#define C_   64
#define HW_  4096
#define K_   512
#define NPIX 131072          // B_*HW_
#define NE   8388608         // B_*C_*HW_
#define TPB  512             // 16 warps -> 4 per SMSP (latency hiding)
#define NBLK (NPIX / TPB)    // 256 blocks

// Scratch (rewritten fully every launch -> deterministic)
__device__ float g_partials[NBLK];
__device__ unsigned int g_count;   // reset to 0 by last block each launch

// ---- packed f32x2 helpers (sm_100+ packed-FP32 pipe) ----
__device__ __forceinline__ unsigned long long fma2(unsigned long long a,
                                                   unsigned long long b,
                                                   unsigned long long c) {
    unsigned long long d;
    asm("fma.rn.f32x2 %0, %1, %2, %3;" : "=l"(d) : "l"(a), "l"(b), "l"(c));
    return d;
}
__device__ __forceinline__ unsigned long long add2(unsigned long long a,
                                                   unsigned long long b) {
    unsigned long long d;
    asm("add.rn.f32x2 %0, %1, %2;" : "=l"(d) : "l"(a), "l"(b));
    return d;
}
__device__ __forceinline__ unsigned long long pack2(float x, float y) {
    unsigned long long u;
    asm("mov.b64 %0, {%1, %2};" : "=l"(u) : "f"(x), "f"(y));
    return u;
}
__device__ __forceinline__ float2 unpack2(unsigned long long u) {
    float2 f;
    asm("mov.b64 {%0, %1}, %2;" : "=f"(f.x), "=f"(f.y) : "l"(u));
    return f;
}

__global__ void __launch_bounds__(TPB, 1)
vq_main(const float* __restrict__ z, const float* __restrict__ cb,
        float* __restrict__ zq_out, float* __restrict__ idx_out,
        float* __restrict__ loss_out) {
    extern __shared__ float sm[];
    float* cbs = sm;             // [K_ * C_] codebook
    float* en  = sm + K_ * C_;   // [K_] ||e_k||^2

    const int tid = threadIdx.x;

    // Stage codebook into SMEM (128 KB)
    {
        float4* dst = (float4*)cbs;
        const float4* src = (const float4*)cb;
        #pragma unroll
        for (int i = tid; i < (K_ * C_) / 4; i += TPB) dst[i] = src[i];
    }
    __syncthreads();

    // ||e_k||^2 per code (identical arithmetic to prior passing kernels)
    for (int k = tid; k < K_; k += TPB) {
        const float* cp = cbs + k * C_;
        float s = 0.f;
        #pragma unroll
        for (int c = 0; c < C_; ++c) s = fmaf(cp[c], cp[c], s);
        en[k] = s;
    }
    __syncthreads();

    // One pixel per thread
    const int p  = blockIdx.x * TPB + tid;
    const int b  = p >> 12;        // / 4096
    const int hw = p & 4095;
    const float* zp = z + (size_t)b * (C_ * HW_) + hw;

    // Load z vector (64 floats, stride HW_) into 32 packed f32x2 regs; ||z||^2
    unsigned long long zr[32];
    float znorm = 0.f;
    #pragma unroll
    for (int i = 0; i < 32; ++i) {
        float x = zp[(2 * i) * HW_];
        float y = zp[(2 * i + 1) * HW_];
        znorm = fmaf(x, x, znorm);
        znorm = fmaf(y, y, znorm);
        zr[i] = pack2(x, y);
    }

    // Argmin over 512 codes (bit-identical accumulation to round-1/2)
    float best  = 3.402823466e38f;
    int   bestk = 0;
    #pragma unroll 1
    for (int k = 0; k < K_; ++k) {
        const ulonglong2* cp = (const ulonglong2*)(cbs + k * C_);
        unsigned long long a0 = 0ull, a1 = 0ull, a2 = 0ull, a3 = 0ull;
        #pragma unroll
        for (int j = 0; j < 16; j += 2) {
            ulonglong2 v0 = cp[j];
            ulonglong2 v1 = cp[j + 1];
            a0 = fma2(zr[2 * j + 0], v0.x, a0);
            a1 = fma2(zr[2 * j + 1], v0.y, a1);
            a2 = fma2(zr[2 * j + 2], v1.x, a2);
            a3 = fma2(zr[2 * j + 3], v1.y, a3);
        }
        a0 = add2(a0, a1);
        a2 = add2(a2, a3);
        a0 = add2(a0, a2);
        float2 f = unpack2(a0);
        float dot  = f.x + f.y;
        float dist = (znorm + en[k]) - 2.0f * dot;
        if (dist < best) { best = dist; bestk = k; }  // strict < -> first-min
    }

    // Epilogue: z_q_st = z + (q - z), per-pixel loss, index
    const float* cbv = cbs + bestk * C_;
    float* zo = zq_out + (size_t)b * (C_ * HW_) + hw;
    float lsum = 0.f;
    #pragma unroll
    for (int i = 0; i < 32; ++i) {
        float2 f = unpack2(zr[i]);
        float d0 = cbv[2 * i]     - f.x;
        float d1 = cbv[2 * i + 1] - f.y;
        lsum = fmaf(d0, d0, lsum);
        lsum = fmaf(d1, d1, lsum);
        zo[(2 * i) * HW_]     = f.x + d0;
        zo[(2 * i + 1) * HW_] = f.y + d1;
    }
    idx_out[p] = (float)bestk;

    // Block loss reduction (16 warps)
    #pragma unroll
    for (int off = 16; off > 0; off >>= 1)
        lsum += __shfl_down_sync(0xFFFFFFFFu, lsum, off);
    __shared__ float red[TPB / 32];
    __shared__ int is_last;
    if ((tid & 31) == 0) red[tid >> 5] = lsum;
    __syncthreads();
    if (tid == 0) {
        float t = 0.f;
        #pragma unroll
        for (int w = 0; w < TPB / 32; ++w) t += red[w];
        g_partials[blockIdx.x] = t;
        __threadfence();
        unsigned int old = atomicAdd(&g_count, 1u);
        is_last = (old == NBLK - 1) ? 1 : 0;
    }
    __syncthreads();

    // Last block: reduce partials -> loss = 1.25 * mean(||z_q - z_e||^2)
    if (is_last) {
        __shared__ float s[NBLK];
        if (tid < NBLK) {
            float v;
            asm volatile("ld.global.cg.f32 %0, [%1];" : "=f"(v) : "l"(g_partials + tid));
            s[tid] = v;
        }
        __syncthreads();
        for (int off = NBLK / 2; off > 0; off >>= 1) {
            if (tid < off) s[tid] += s[tid + off];
            __syncthreads();
        }
        if (tid == 0) {
            float q = s[0] / (float)NE;   // q_loss == e_loss numerically
            loss_out[0] = q + 0.25f * q;
            g_count = 0;                  // reset for next graph replay
        }
    }
}

extern "C" void kernel_launch(void* const* d_in, const int* in_sizes, int n_in,
                              void* d_out, int out_size) {
    const float* z  = (const float*)d_in[0];   // z_e [32,64,64,64] f32
    const float* cb = (const float*)d_in[1];   // codebook [512,64] f32
    float* out  = (float*)d_out;
    float* zq   = out;               // [NE]
    float* idx  = out + NE;          // [NPIX]
    float* loss = out + NE + NPIX;   // [1]

    const int smem_bytes = (K_ * C_ + K_) * (int)sizeof(float);  // 133120
    cudaFuncSetAttribute(vq_main, cudaFuncAttributeMaxDynamicSharedMemorySize, smem_bytes);
    vq_main<<<NBLK, TPB, smem_bytes>>>(z, cb, zq, idx, loss);
}

// round 4
// speedup vs baseline: 1.2297x; 1.2297x over previous
#include <cuda_runtime.h>

// Problem shape (fixed)
#define B_   32
#define C_   64
#define HW_  4096
#define K_   512
#define NPIX 131072          // B_*HW_
#define NE   8388608         // B_*C_*HW_
#define TPB  256
#define PPT  2               // pixels per thread (best LDS:FMA ratio)
#define PIX_PER_BLK (TPB * PPT)   // 512
#define NBLK (NPIX / PIX_PER_BLK) // 256

// Scratch (rewritten fully every launch -> deterministic)
__device__ float g_partials[NBLK];
__device__ unsigned int g_count;   // reset to 0 by last block each launch

// ---- packed f32x2 helpers ----
__device__ __forceinline__ unsigned long long fma2(unsigned long long a,
                                                   unsigned long long b,
                                                   unsigned long long c) {
    unsigned long long d;
    asm("fma.rn.f32x2 %0, %1, %2, %3;" : "=l"(d) : "l"(a), "l"(b), "l"(c));
    return d;
}
__device__ __forceinline__ unsigned long long add2(unsigned long long a,
                                                   unsigned long long b) {
    unsigned long long d;
    asm("add.rn.f32x2 %0, %1, %2;" : "=l"(d) : "l"(a), "l"(b));
    return d;
}
__device__ __forceinline__ unsigned long long pack2(float x, float y) {
    unsigned long long u;
    asm("mov.b64 %0, {%1, %2};" : "=l"(u) : "f"(x), "f"(y));
    return u;
}
__device__ __forceinline__ float2 unpack2(unsigned long long u) {
    float2 f;
    asm("mov.b64 {%0, %1}, %2;" : "=f"(f.x), "=f"(f.y) : "l"(u));
    return f;
}

__global__ void __launch_bounds__(TPB, 1)
vq_main(const float* __restrict__ z, const float* __restrict__ cb,
        float* __restrict__ zq_out, float* __restrict__ idx_out,
        float* __restrict__ loss_out) {
    extern __shared__ float sm[];
    float* cbs = sm;             // [K_ * C_] codebook
    float* en  = sm + K_ * C_;   // [K_] ||e_k||^2

    const int tid = threadIdx.x;

    // Stage codebook into SMEM (128 KB)
    {
        float4* dst = (float4*)cbs;
        const float4* src = (const float4*)cb;
        #pragma unroll
        for (int i = tid; i < (K_ * C_) / 4; i += TPB) dst[i] = src[i];
    }
    __syncthreads();

    // ||e_k||^2 per code (identical arithmetic to prior passing kernels)
    for (int k = tid; k < K_; k += TPB) {
        const float* cp = cbs + k * C_;
        float s = 0.f;
        #pragma unroll
        for (int c = 0; c < C_; ++c) s = fmaf(cp[c], cp[c], s);
        en[k] = s;
    }
    __syncthreads();

    // Two pixels per thread, 512 consecutive pixels per block (same batch b)
    const int p0  = blockIdx.x * PIX_PER_BLK + tid;
    const int p1  = p0 + TPB;
    const int b   = p0 >> 12;
    const int hw0 = p0 & 4095;
    const int hw1 = p1 & 4095;
    const float* zbp = z + (size_t)b * (C_ * HW_);
    const float* zp0 = zbp + hw0;
    const float* zp1 = zbp + hw1;

    // Load both z vectors into packed f32x2 regs; ||z||^2 per pixel
    unsigned long long za[32], zc[32];
    float zn0 = 0.f, zn1 = 0.f;
    #pragma unroll
    for (int i = 0; i < 32; ++i) {
        float x0 = zp0[(2 * i) * HW_];
        float y0 = zp0[(2 * i + 1) * HW_];
        float x1 = zp1[(2 * i) * HW_];
        float y1 = zp1[(2 * i + 1) * HW_];
        zn0 = fmaf(x0, x0, zn0); zn0 = fmaf(y0, y0, zn0);
        zn1 = fmaf(x1, x1, zn1); zn1 = fmaf(y1, y1, zn1);
        za[i] = pack2(x0, y0);
        zc[i] = pack2(x1, y1);
    }

    // Argmin over 512 codes, 2 codes per iteration for in-warp ILP.
    // Per-(pixel,code) accumulation is bit-identical to the round-2 kernel.
    float best0 = 3.402823466e38f, best1 = 3.402823466e38f;
    int   bk0 = 0, bk1 = 0;
    #pragma unroll 1
    for (int k = 0; k < K_; k += 2) {
        const ulonglong2* cpA = (const ulonglong2*)(cbs + k * C_);
        const ulonglong2* cpB = cpA + 16;   // code k+1 (64 floats = 16 ulonglong2)

        unsigned long long aA0 = 0ull, aA1 = 0ull, aA2 = 0ull, aA3 = 0ull;  // pix0,codeA
        unsigned long long cA0 = 0ull, cA1 = 0ull, cA2 = 0ull, cA3 = 0ull;  // pix1,codeA
        unsigned long long aB0 = 0ull, aB1 = 0ull, aB2 = 0ull, aB3 = 0ull;  // pix0,codeB
        unsigned long long cB0 = 0ull, cB1 = 0ull, cB2 = 0ull, cB3 = 0ull;  // pix1,codeB

        #pragma unroll
        for (int j = 0; j < 16; j += 2) {
            ulonglong2 vA0 = cpA[j];
            ulonglong2 vA1 = cpA[j + 1];
            ulonglong2 vB0 = cpB[j];
            ulonglong2 vB1 = cpB[j + 1];

            aA0 = fma2(za[2 * j + 0], vA0.x, aA0);
            aA1 = fma2(za[2 * j + 1], vA0.y, aA1);
            aA2 = fma2(za[2 * j + 2], vA1.x, aA2);
            aA3 = fma2(za[2 * j + 3], vA1.y, aA3);
            cA0 = fma2(zc[2 * j + 0], vA0.x, cA0);
            cA1 = fma2(zc[2 * j + 1], vA0.y, cA1);
            cA2 = fma2(zc[2 * j + 2], vA1.x, cA2);
            cA3 = fma2(zc[2 * j + 3], vA1.y, cA3);

            aB0 = fma2(za[2 * j + 0], vB0.x, aB0);
            aB1 = fma2(za[2 * j + 1], vB0.y, aB1);
            aB2 = fma2(za[2 * j + 2], vB1.x, aB2);
            aB3 = fma2(za[2 * j + 3], vB1.y, aB3);
            cB0 = fma2(zc[2 * j + 0], vB0.x, cB0);
            cB1 = fma2(zc[2 * j + 1], vB0.y, cB1);
            cB2 = fma2(zc[2 * j + 2], vB1.x, cB2);
            cB3 = fma2(zc[2 * j + 3], vB1.y, cB3);
        }

        float ekA = en[k];
        float ekB = en[k + 1];

        aA0 = add2(aA0, aA1); aA2 = add2(aA2, aA3); aA0 = add2(aA0, aA2);
        cA0 = add2(cA0, cA1); cA2 = add2(cA2, cA3); cA0 = add2(cA0, cA2);
        aB0 = add2(aB0, aB1); aB2 = add2(aB2, aB3); aB0 = add2(aB0, aB2);
        cB0 = add2(cB0, cB1); cB2 = add2(cB2, cB3); cB0 = add2(cB0, cB2);

        float2 fA0 = unpack2(aA0);
        float2 fA1 = unpack2(cA0);
        float2 fB0 = unpack2(aB0);
        float2 fB1 = unpack2(cB0);

        float dA0 = (zn0 + ekA) - 2.0f * (fA0.x + fA0.y);
        float dA1 = (zn1 + ekA) - 2.0f * (fA1.x + fA1.y);
        float dB0 = (zn0 + ekB) - 2.0f * (fB0.x + fB0.y);
        float dB1 = (zn1 + ekB) - 2.0f * (fB1.x + fB1.y);

        // Compare code k before k+1: strict < preserves first-min semantics
        if (dA0 < best0) { best0 = dA0; bk0 = k; }
        if (dB0 < best0) { best0 = dB0; bk0 = k + 1; }
        if (dA1 < best1) { best1 = dA1; bk1 = k; }
        if (dB1 < best1) { best1 = dB1; bk1 = k + 1; }
    }

    // Epilogue: z_q_st = z + (q - z), per-pixel loss, index (same rounding as before)
    float lsum = 0.f;
    {
        const float* cbv = cbs + bk0 * C_;
        float* zo = zq_out + (size_t)b * (C_ * HW_) + hw0;
        #pragma unroll
        for (int i = 0; i < 32; ++i) {
            float2 f = unpack2(za[i]);
            float d0 = cbv[2 * i]     - f.x;
            float d1 = cbv[2 * i + 1] - f.y;
            lsum = fmaf(d0, d0, lsum);
            lsum = fmaf(d1, d1, lsum);
            zo[(2 * i) * HW_]     = f.x + d0;
            zo[(2 * i + 1) * HW_] = f.y + d1;
        }
        idx_out[p0] = (float)bk0;
    }
    {
        const float* cbv = cbs + bk1 * C_;
        float* zo = zq_out + (size_t)b * (C_ * HW_) + hw1;
        #pragma unroll
        for (int i = 0; i < 32; ++i) {
            float2 f = unpack2(zc[i]);
            float d0 = cbv[2 * i]     - f.x;
            float d1 = cbv[2 * i + 1] - f.y;
            lsum = fmaf(d0, d0, lsum);
            lsum = fmaf(d1, d1, lsum);
            zo[(2 * i) * HW_]     = f.x + d0;
            zo[(2 * i + 1) * HW_] = f.y + d1;
        }
        idx_out[p1] = (float)bk1;
    }

    // Block loss reduction
    #pragma unroll
    for (int off = 16; off > 0; off >>= 1)
        lsum += __shfl_down_sync(0xFFFFFFFFu, lsum, off);
    __shared__ float red[TPB / 32];
    __shared__ int is_last;
    if ((tid & 31) == 0) red[tid >> 5] = lsum;
    __syncthreads();
    if (tid == 0) {
        float t = 0.f;
        #pragma unroll
        for (int w = 0; w < TPB / 32; ++w) t += red[w];
        g_partials[blockIdx.x] = t;
        __threadfence();
        unsigned int old = atomicAdd(&g_count, 1u);
        is_last = (old == NBLK - 1) ? 1 : 0;
    }
    __syncthreads();

    // Last block: reduce partials -> loss = 1.25 * mean(||z_q - z_e||^2)
    if (is_last) {
        __shared__ float s[TPB];
        float v;
        asm volatile("ld.global.cg.f32 %0, [%1];" : "=f"(v) : "l"(g_partials + tid));
        s[tid] = v;
        __syncthreads();
        for (int off = TPB / 2; off > 0; off >>= 1) {
            if (tid < off) s[tid] += s[tid + off];
            __syncthreads();
        }
        if (tid == 0) {
            float q = s[0] / (float)NE;   // q_loss == e_loss numerically
            loss_out[0] = q + 0.25f * q;
            g_count = 0;                  // reset for next graph replay
        }
    }
}

extern "C" void kernel_launch(void* const* d_in, const int* in_sizes, int n_in,
                              void* d_out, int out_size) {
    const float* z  = (const float*)d_in[0];   // z_e [32,64,64,64] f32
    const float* cb = (const float*)d_in[1];   // codebook [512,64] f32
    float* out  = (float*)d_out;
    float* zq   = out;               // [NE]
    float* idx  = out + NE;          // [NPIX]
    float* loss = out + NE + NPIX;   // [1]

    const int smem_bytes = (K_ * C_ + K_) * (int)sizeof(float);  // 133120
    cudaFuncSetAttribute(vq_main, cudaFuncAttributeMaxDynamicSharedMemorySize, smem_bytes);
    vq_main<<<NBLK, TPB, smem_bytes>>>(z, cb, zq, idx, loss);
}